// round 3
// baseline (speedup 1.0000x reference)
#include <cuda_runtime.h>
#include <math.h>
#include <stdint.h>
#include <string.h>

// ---------------- problem constants ----------------
#define N_PTS   29696
#define N_IN_C  1024
#define E1_C    512
#define E2_C    512
#define E3_C    2048
#define NZ_C    32
#define D1_C    2048
#define D2_C    512
#define D3_C    512
#define K_C     100
#define EPS_C   1e-5f

// FFMA2 GEMM tiling: 128x128 tile, TK=8, 256 threads, 8x8 microtile, double-buffered
#define TM 128
#define TN 128
#define TK 8
#define MBLK (N_PTS / TM)                       // 232
#define MSE_PARTIALS (MBLK * (N_IN_C / TN))     // 232*8 = 1856

// small GEMM (N=32 layer) tiling
#define BM 128
#define BN 64
#define BK 16

// ---------------- scratch ----------------
__device__ float g_bufA[(size_t)N_PTS * 2048];
__device__ float g_bufB[(size_t)N_PTS * 2048];
__device__ float g_zbuf[(size_t)N_PTS * NZ_C];
__device__ float g_q[(size_t)K_C * N_PTS];      // TRANSPOSED: [K][N]
__device__ int   g_pred[N_PTS];
__device__ float g_Scon[N_PTS];
__device__ float g_u[K_C];
__device__ float g_f[K_C];
__device__ int   g_cnt[K_C];
__device__ float g_S;
__device__ float g_uloss;
__device__ float g_msep[MSE_PARTIALS];
__device__ float g_klp[MBLK];

__global__ void init_kernel() {
    int t = threadIdx.x;
    if (t < K_C) g_cnt[t] = 0;
}

// ---------------- packed fp32 helpers ----------------
__device__ __forceinline__ void ffma2(unsigned long long& acc,
                                      unsigned long long a,
                                      unsigned long long b) {
    asm("fma.rn.f32x2 %0, %1, %2, %0;" : "+l"(acc) : "l"(a), "l"(b));
}
union F4U {
    float4 f;
    unsigned long long u[2];
};

// ---------------- inner tile compute ----------------
__device__ __forceinline__ void compute_tile(
    const float (&As2)[TK][2 * TM], const float (&Ws)[TK][TN],
    unsigned long long (&acc)[8][4], int tx, int ty)
{
#pragma unroll
    for (int kk = 0; kk < TK; kk++) {
        F4U b0, b1;
        b0.f = *reinterpret_cast<const float4*>(&Ws[kk][tx * 4]);
        b1.f = *reinterpret_cast<const float4*>(&Ws[kk][64 + tx * 4]);
#pragma unroll
        for (int i = 0; i < 4; i++) {
            F4U a;
            a.f = *reinterpret_cast<const float4*>(&As2[kk][(ty * 8 + 2 * i) * 2]);
            ffma2(acc[2 * i][0],     a.u[0], b0.u[0]);
            ffma2(acc[2 * i][1],     a.u[0], b0.u[1]);
            ffma2(acc[2 * i][2],     a.u[0], b1.u[0]);
            ffma2(acc[2 * i][3],     a.u[0], b1.u[1]);
            ffma2(acc[2 * i + 1][0], a.u[1], b0.u[0]);
            ffma2(acc[2 * i + 1][1], a.u[1], b0.u[1]);
            ffma2(acc[2 * i + 1][2], a.u[1], b1.u[0]);
            ffma2(acc[2 * i + 1][3], a.u[1], b1.u[1]);
        }
    }
}

// ---------------- FFMA2 GEMM, double-buffered ----------------
// requires M%128==0, K%8==0, N%128==0
template <int DORELU, int DOMSE>
__global__ __launch_bounds__(256, 2) void gemm_ffma2(
    const float* __restrict__ A, const float* __restrict__ W,
    const float* __restrict__ bias, float* __restrict__ C,
    const float* __restrict__ Xref, float* __restrict__ partial,
    int M, int K, int N)
{
    __shared__ float As2[2][TK][2 * TM];   // duplicated A: 16 KB
    __shared__ float Ws[2][TK][TN];        // 8 KB
    const int tid = threadIdx.x;
    const int rowBlock = blockIdx.y * TM;
    const int colBlock = blockIdx.x * TN;
    const int tx = tid & 15;
    const int ty = tid >> 4;

    unsigned long long acc[8][4];
#pragma unroll
    for (int i = 0; i < 8; i++)
#pragma unroll
        for (int g = 0; g < 4; g++) acc[i][g] = 0ull;

    // global-load mappings
    const int aRow = tid >> 1;            // 0..127
    const int aKof = (tid & 1) * 4;       // 0 or 4
    const int wK   = tid >> 5;            // 0..7
    const int wC   = (tid & 31) * 4;      // 0..124

    const float* aPtr = &A[(size_t)(rowBlock + aRow) * K + aKof];
    const float* wPtr = &W[(size_t)wK * N + colBlock + wC];

    // prologue: tile 0
    {
        float4 av = *reinterpret_cast<const float4*>(aPtr);
        float4 wv = *reinterpret_cast<const float4*>(wPtr);
        *reinterpret_cast<float2*>(&As2[0][aKof + 0][2 * aRow]) = make_float2(av.x, av.x);
        *reinterpret_cast<float2*>(&As2[0][aKof + 1][2 * aRow]) = make_float2(av.y, av.y);
        *reinterpret_cast<float2*>(&As2[0][aKof + 2][2 * aRow]) = make_float2(av.z, av.z);
        *reinterpret_cast<float2*>(&As2[0][aKof + 3][2 * aRow]) = make_float2(av.w, av.w);
        *reinterpret_cast<float4*>(&Ws[0][wK][wC]) = wv;
    }
    __syncthreads();

    int buf = 0;
    for (int k0 = TK; k0 < K; k0 += TK) {
        float4 av = *reinterpret_cast<const float4*>(aPtr + k0);
        float4 wv = *reinterpret_cast<const float4*>(wPtr + (size_t)k0 * N);
        compute_tile(As2[buf], Ws[buf], acc, tx, ty);
        int nb = buf ^ 1;
        *reinterpret_cast<float2*>(&As2[nb][aKof + 0][2 * aRow]) = make_float2(av.x, av.x);
        *reinterpret_cast<float2*>(&As2[nb][aKof + 1][2 * aRow]) = make_float2(av.y, av.y);
        *reinterpret_cast<float2*>(&As2[nb][aKof + 2][2 * aRow]) = make_float2(av.z, av.z);
        *reinterpret_cast<float2*>(&As2[nb][aKof + 3][2 * aRow]) = make_float2(av.w, av.w);
        *reinterpret_cast<float4*>(&Ws[nb][wK][wC]) = wv;
        __syncthreads();
        buf = nb;
    }
    compute_tile(As2[buf], Ws[buf], acc, tx, ty);

    // epilogue
    const int rBase = ty * 8;
    float4 bs0 = *reinterpret_cast<const float4*>(&bias[colBlock + tx * 4]);
    float4 bs1 = *reinterpret_cast<const float4*>(&bias[colBlock + 64 + tx * 4]);

    if (DOMSE) {
        __shared__ float red[256];
        float mse = 0.f;
#pragma unroll
        for (int i = 0; i < 8; i++) {
            const float* xrow = &Xref[(size_t)(rowBlock + rBase + i) * N + colBlock];
            float4 x0 = *reinterpret_cast<const float4*>(&xrow[tx * 4]);
            float4 x1 = *reinterpret_cast<const float4*>(&xrow[64 + tx * 4]);
            F4U v0, v1;
            v0.u[0] = acc[i][0]; v0.u[1] = acc[i][1];
            v1.u[0] = acc[i][2]; v1.u[1] = acc[i][3];
            float d;
            d = v0.f.x + bs0.x - x0.x; mse = fmaf(d, d, mse);
            d = v0.f.y + bs0.y - x0.y; mse = fmaf(d, d, mse);
            d = v0.f.z + bs0.z - x0.z; mse = fmaf(d, d, mse);
            d = v0.f.w + bs0.w - x0.w; mse = fmaf(d, d, mse);
            d = v1.f.x + bs1.x - x1.x; mse = fmaf(d, d, mse);
            d = v1.f.y + bs1.y - x1.y; mse = fmaf(d, d, mse);
            d = v1.f.z + bs1.z - x1.z; mse = fmaf(d, d, mse);
            d = v1.f.w + bs1.w - x1.w; mse = fmaf(d, d, mse);
        }
        red[tid] = mse;
        __syncthreads();
        for (int o = 128; o > 0; o >>= 1) {
            if (tid < o) red[tid] += red[tid + o];
            __syncthreads();
        }
        if (tid == 0) partial[blockIdx.y * gridDim.x + blockIdx.x] = red[0];
    } else {
#pragma unroll
        for (int i = 0; i < 8; i++) {
            float* crow = &C[(size_t)(rowBlock + rBase + i) * N + colBlock];
            F4U v0, v1;
            v0.u[0] = acc[i][0]; v0.u[1] = acc[i][1];
            v1.u[0] = acc[i][2]; v1.u[1] = acc[i][3];
            v0.f.x += bs0.x; v0.f.y += bs0.y; v0.f.z += bs0.z; v0.f.w += bs0.w;
            v1.f.x += bs1.x; v1.f.y += bs1.y; v1.f.z += bs1.z; v1.f.w += bs1.w;
            if (DORELU) {
                v0.f.x = fmaxf(v0.f.x, 0.f); v0.f.y = fmaxf(v0.f.y, 0.f);
                v0.f.z = fmaxf(v0.f.z, 0.f); v0.f.w = fmaxf(v0.f.w, 0.f);
                v1.f.x = fmaxf(v1.f.x, 0.f); v1.f.y = fmaxf(v1.f.y, 0.f);
                v1.f.z = fmaxf(v1.f.z, 0.f); v1.f.w = fmaxf(v1.f.w, 0.f);
            }
            *reinterpret_cast<float4*>(&crow[tx * 4]) = v0.f;
            *reinterpret_cast<float4*>(&crow[64 + tx * 4]) = v1.f;
        }
    }
}

// ---------------- small-N fp32 GEMM (N=32 z layer) ----------------
__global__ __launch_bounds__(256) void gemm_relu(
    const float* __restrict__ A, const float* __restrict__ W,
    const float* __restrict__ bias, float* __restrict__ C,
    int M, int K, int N, int doRelu)
{
    __shared__ float As[BK][BM];
    __shared__ float Wsm[BK][BN];
    const int tid = threadIdx.x;
    const int rowBlock = blockIdx.y * BM;
    const int colBlock = blockIdx.x * BN;
    const int tx = tid & 15;
    const int ty = tid >> 4;
    const int rBase = ty * 8;
    const int cBase = tx * 4;

    float acc[8][4];
#pragma unroll
    for (int i = 0; i < 8; i++)
#pragma unroll
        for (int j = 0; j < 4; j++) acc[i][j] = 0.f;

    const int aRow0 = tid >> 2;
    const int aF4   = tid & 3;
    const int wK    = tid >> 4;
    const int wC    = (tid & 15) * 4;

    for (int k0 = 0; k0 < K; k0 += BK) {
#pragma unroll
        for (int h = 0; h < 2; h++) {
            int r = aRow0 + h * 64;
            float4 v = *reinterpret_cast<const float4*>(
                &A[(size_t)(rowBlock + r) * K + k0 + aF4 * 4]);
            As[aF4 * 4 + 0][r] = v.x;
            As[aF4 * 4 + 1][r] = v.y;
            As[aF4 * 4 + 2][r] = v.z;
            As[aF4 * 4 + 3][r] = v.w;
        }
        {
            int col = colBlock + wC;
            float4 v = make_float4(0.f, 0.f, 0.f, 0.f);
            if (col + 3 < N) {
                v = *reinterpret_cast<const float4*>(&W[(size_t)(k0 + wK) * N + col]);
            } else {
                float tmp[4] = {0.f, 0.f, 0.f, 0.f};
                for (int j = 0; j < 4; j++)
                    if (col + j < N) tmp[j] = W[(size_t)(k0 + wK) * N + col + j];
                v = make_float4(tmp[0], tmp[1], tmp[2], tmp[3]);
            }
            *reinterpret_cast<float4*>(&Wsm[wK][wC]) = v;
        }
        __syncthreads();
#pragma unroll
        for (int kk = 0; kk < BK; kk++) {
            float a[8], b[4];
#pragma unroll
            for (int i = 0; i < 8; i++) a[i] = As[kk][rBase + i];
#pragma unroll
            for (int j = 0; j < 4; j++) b[j] = Wsm[kk][cBase + j];
#pragma unroll
            for (int i = 0; i < 8; i++)
#pragma unroll
                for (int j = 0; j < 4; j++) acc[i][j] = fmaf(a[i], b[j], acc[i][j]);
        }
        __syncthreads();
    }
#pragma unroll
    for (int i = 0; i < 8; i++) {
        int row = rowBlock + rBase + i;
#pragma unroll
        for (int j = 0; j < 4; j++) {
            int col = colBlock + cBase + j;
            if (col < N) {
                float v = acc[i][j] + bias[col];
                if (doRelu) v = fmaxf(v, 0.f);
                C[(size_t)row * N + col] = v;
            }
        }
    }
}

// ---------------- pass A: per-point clustering stats (q transposed [K][N]) ----------------
__global__ __launch_bounds__(128) void passA(
    const float* __restrict__ z, const float* __restrict__ t1,
    const float* __restrict__ clus, float* __restrict__ q,
    int* __restrict__ pred, float* __restrict__ scon,
    float* __restrict__ out, int out_size)
{
    __shared__ float cs[K_C * NZ_C];
    const int tid = threadIdx.x;
    for (int i = tid; i < K_C * NZ_C; i += 128) cs[i] = clus[i];
    __syncthreads();

    const int n = blockIdx.x * 128 + tid;
    if (n >= N_PTS) return;

    const float tx = t1[n * 3 + 0] * 0.01f;
    const float ty = t1[n * 3 + 1] * 0.01f;
    const float tz = t1[n * 3 + 2] * 0.01f;
    const float cm = tx * ty * tz * 0.99f + 1.0f;

    float zp[NZ_C];
    const float* zr = &z[(size_t)n * NZ_C];
    float mean = 0.f;
#pragma unroll
    for (int i = 0; i < NZ_C; i++) { zp[i] = zr[i] * cm; mean += zp[i]; }
    mean *= (1.0f / NZ_C);
    float var = 0.f;
#pragma unroll
    for (int i = 0; i < NZ_C; i++) { float d = zp[i] - mean; var += d * d; }
    var *= (1.0f / (NZ_C - 1));
    const float invstd = 1.0f / sqrtf(var);
#pragma unroll
    for (int i = 0; i < NZ_C; i++) zp[i] = (zp[i] - mean) * invstd;

    float qsum = 0.f;
    float best = -1.f;
    int bestk = 0;
    for (int k = 0; k < K_C; k++) {
        const float* c = &cs[k * NZ_C];
        float d = 0.f;
#pragma unroll
        for (int i = 0; i < NZ_C; i++) { float df = zp[i] - c[i]; d = fmaf(df, df, d); }
        float qr = EPS_C + d;
        q[(size_t)k * N_PTS + n] = qr;   // coalesced store
        qsum += qr;
        if (qr > best) { best = qr; bestk = k; }
    }
    const float inv = 1.0f / qsum;
    float s = 0.f;
    for (int k = 0; k < K_C; k++) {
        float qn = q[(size_t)k * N_PTS + n] * inv;
        q[(size_t)k * N_PTS + n] = qn;
        float l = logf(qn);
        float t = 1.0f - qn;
        float neg_temp = t * t * (-l) * (float)N_PTS;
        s += 1.0f / sqrtf(neg_temp);
    }
    pred[n] = bestk;
    scon[n] = s;
    if (n < out_size) out[n] = (float)bestk;
    atomicAdd(&g_cnt[bestk], 1);
}

// ---------------- u[k] = sum_n q[k][n] (coalesced) ----------------
__global__ void ureduce(const float* __restrict__ q) {
    __shared__ float sh[256];
    const int k = blockIdx.x;
    float s = 0.f;
    for (int n = threadIdx.x; n < N_PTS; n += 256) s += q[(size_t)k * N_PTS + n];
    sh[threadIdx.x] = s;
    __syncthreads();
    for (int o = 128; o > 0; o >>= 1) {
        if (threadIdx.x < o) sh[threadIdx.x] += sh[threadIdx.x + o];
        __syncthreads();
    }
    if (threadIdx.x == 0) g_u[k] = sh[0];
}

__global__ void sreduce(const float* __restrict__ scon) {
    __shared__ float sh[256];
    float s = 0.f;
    for (int n = threadIdx.x; n < N_PTS; n += 256) s += scon[n];
    sh[threadIdx.x] = s;
    __syncthreads();
    for (int o = 128; o > 0; o >>= 1) {
        if (threadIdx.x < o) sh[threadIdx.x] += sh[threadIdx.x + o];
        __syncthreads();
    }
    if (threadIdx.x == 0) g_S = sh[0];
}

// ---------------- pass B: f[k], u_loss ----------------
__global__ void passB(const float* __restrict__ clus) {
    __shared__ float sh[256];
    const int tid = threadIdx.x;
    float s = 0.f;
    for (int p = tid; p < K_C * K_C; p += 256) {
        int i = p / K_C, j = p - i * K_C;
        const float* a = &clus[i * NZ_C];
        const float* b = &clus[j * NZ_C];
        float d = 0.f;
#pragma unroll
        for (int t = 0; t < NZ_C; t++) { float df = a[t] - b[t]; d = fmaf(df, df, d); }
        s += d;
    }
    sh[tid] = s;
    __syncthreads();
    for (int o = 128; o > 0; o >>= 1) {
        if (tid < o) sh[tid] += sh[tid + o];
        __syncthreads();
    }
    if (tid == 0) {
        float md = sh[0] / (float)(K_C * K_C - K_C);
        g_uloss = 0.01f / md;

        float un[K_C], vn[K_C];
        float um = 0.f;
        for (int k = 0; k < K_C; k++) um += g_u[k];
        um /= (float)K_C;
        float uv = 0.f;
        for (int k = 0; k < K_C; k++) { float d = g_u[k] - um; uv += d * d; }
        uv /= (float)(K_C - 1);
        float uis = 1.0f / sqrtf(uv);
        for (int k = 0; k < K_C; k++) un[k] = (g_u[k] - um) * uis;

        float S = g_S;
        float vm = 0.f;
        for (int k = 0; k < K_C; k++) {
            float nc = (g_cnt[k] > 0) ? (float)g_cnt[k] : 1.0f;
            vn[k] = sqrtf(nc) * S;
            vm += vn[k];
        }
        vm /= (float)K_C;
        float vv = 0.f;
        for (int k = 0; k < K_C; k++) { float d = vn[k] - vm; vv += d * d; }
        vv /= (float)(K_C - 1);
        float vis = 1.0f / sqrtf(vv);
        for (int k = 0; k < K_C; k++) vn[k] = (vn[k] - vm) * vis;

        float umin = un[0], vmin = vn[0];
        for (int k = 1; k < K_C; k++) {
            umin = fminf(umin, un[k]);
            vmin = fminf(vmin, vn[k]);
        }
        for (int k = 0; k < K_C; k++) {
            g_f[k] = (un[k] - umin + 0.001f) + (vn[k] - vmin + 0.001f) + 1.0f;
        }
    }
}

// ---------------- pass C: KL partials (q transposed) ----------------
__global__ __launch_bounds__(128) void passC(const float* __restrict__ q,
                                             float* __restrict__ klp) {
    __shared__ float fsh[K_C];
    __shared__ float sh[128];
    const int tid = threadIdx.x;
    for (int i = tid; i < K_C; i += 128) fsh[i] = g_f[i];
    __syncthreads();
    const int n = blockIdx.x * 128 + tid;
    float kl = 0.f;
    float ws = 0.f;
    for (int k = 0; k < K_C; k++) {
        float qv = q[(size_t)k * N_PTS + n];
        ws += qv * qv / fsh[k];
    }
    float inv = 1.0f / ws;
    for (int k = 0; k < K_C; k++) {
        float qv = q[(size_t)k * N_PTS + n];
        float p = qv * qv / fsh[k] * inv;
        kl += p * (logf(p) - logf(qv));
    }
    sh[tid] = kl;
    __syncthreads();
    for (int o = 64; o > 0; o >>= 1) {
        if (tid < o) sh[tid] += sh[tid + o];
        __syncthreads();
    }
    if (tid == 0) klp[blockIdx.x] = sh[0];
}

// ---------------- final: loss scalar ----------------
__global__ void finalk(float* __restrict__ out, int out_size) {
    __shared__ float sh[256];
    __shared__ float tot[2];
    const int tid = threadIdx.x;
    float s = 0.f;
    for (int i = tid; i < MSE_PARTIALS; i += 256) s += g_msep[i];
    sh[tid] = s;
    __syncthreads();
    for (int o = 128; o > 0; o >>= 1) {
        if (tid < o) sh[tid] += sh[tid + o];
        __syncthreads();
    }
    if (tid == 0) tot[0] = sh[0];
    __syncthreads();
    s = 0.f;
    for (int i = tid; i < MBLK; i += 256) s += g_klp[i];
    sh[tid] = s;
    __syncthreads();
    for (int o = 128; o > 0; o >>= 1) {
        if (tid < o) sh[tid] += sh[tid + o];
        __syncthreads();
    }
    if (tid == 0) tot[1] = sh[0];
    __syncthreads();
    if (tid == 0) {
        float re_loss = tot[0] / ((float)N_PTS * (float)N_IN_C);
        float kl_loss = tot[1] / ((float)N_PTS * (float)K_C) * 0.01f;
        float loss = kl_loss + re_loss + g_uloss;
        if (out_size > N_PTS) out[N_PTS] = loss;
    }
}

// ---------------- launch ----------------
extern "C" void kernel_launch(void* const* d_in, const int* in_sizes, int n_in,
                              void* d_out, int out_size) {
    const float* x    = (const float*)d_in[0];
    const float* t1   = (const float*)d_in[1];
    const float* clus = (const float*)d_in[2];
    const float* We1  = (const float*)d_in[3];
    const float* be1  = (const float*)d_in[4];
    const float* We2  = (const float*)d_in[5];
    const float* be2  = (const float*)d_in[6];
    const float* We3  = (const float*)d_in[7];
    const float* be3  = (const float*)d_in[8];
    const float* Wz   = (const float*)d_in[9];
    const float* bz   = (const float*)d_in[10];
    const float* Wd1  = (const float*)d_in[11];
    const float* bd1  = (const float*)d_in[12];
    const float* Wd2  = (const float*)d_in[13];
    const float* bd2  = (const float*)d_in[14];
    const float* Wd3  = (const float*)d_in[15];
    const float* bd3  = (const float*)d_in[16];
    const float* Wxb  = (const float*)d_in[17];
    const float* bxb  = (const float*)d_in[18];
    float* out = (float*)d_out;

    float *bufA, *bufB, *zbuf, *qbuf, *scon, *msep, *klp;
    int *pred;
    cudaGetSymbolAddress((void**)&bufA, g_bufA);
    cudaGetSymbolAddress((void**)&bufB, g_bufB);
    cudaGetSymbolAddress((void**)&zbuf, g_zbuf);
    cudaGetSymbolAddress((void**)&qbuf, g_q);
    cudaGetSymbolAddress((void**)&pred, g_pred);
    cudaGetSymbolAddress((void**)&scon, g_Scon);
    cudaGetSymbolAddress((void**)&msep, g_msep);
    cudaGetSymbolAddress((void**)&klp,  g_klp);

    init_kernel<<<1, 128>>>();

    // encoder
    gemm_ffma2<1, 0><<<dim3(E1_C / TN, MBLK), 256>>>(x,    We1, be1, bufA, nullptr, nullptr, N_PTS, N_IN_C, E1_C);
    gemm_ffma2<1, 0><<<dim3(E2_C / TN, MBLK), 256>>>(bufA, We2, be2, bufB, nullptr, nullptr, N_PTS, E1_C,  E2_C);
    gemm_ffma2<1, 0><<<dim3(E3_C / TN, MBLK), 256>>>(bufB, We3, be3, bufA, nullptr, nullptr, N_PTS, E2_C,  E3_C);
    gemm_relu<<<dim3(1, N_PTS / BM), 256>>>(bufA, Wz, bz, zbuf, N_PTS, E3_C, NZ_C, 0);
    // decoder
    gemm_ffma2<1, 0><<<dim3(D1_C / TN, MBLK), 256>>>(zbuf, Wd1, bd1, bufB, nullptr, nullptr, N_PTS, NZ_C, D1_C);
    gemm_ffma2<1, 0><<<dim3(D2_C / TN, MBLK), 256>>>(bufB, Wd2, bd2, bufA, nullptr, nullptr, N_PTS, D1_C, D2_C);
    gemm_ffma2<1, 0><<<dim3(D3_C / TN, MBLK), 256>>>(bufA, Wd3, bd3, bufB, nullptr, nullptr, N_PTS, D2_C, D3_C);
    gemm_ffma2<0, 1><<<dim3(N_IN_C / TN, MBLK), 256>>>(bufB, Wxb, bxb, nullptr, x, msep, N_PTS, D3_C, N_IN_C);

    // clustering
    passA<<<MBLK, 128>>>(zbuf, t1, clus, qbuf, pred, scon, out, out_size);
    ureduce<<<K_C, 256>>>(qbuf);
    sreduce<<<1, 256>>>(scon);
    passB<<<1, 256>>>(clus);
    passC<<<MBLK, 128>>>(qbuf, klp);
    finalk<<<1, 256>>>(out, out_size);
}

// round 4
// speedup vs baseline: 1.0007x; 1.0007x over previous
#include <cuda_runtime.h>
#include <math.h>
#include <stdint.h>
#include <string.h>

// ---------------- problem constants ----------------
#define N_PTS   29696
#define N_IN_C  1024
#define E1_C    512
#define E2_C    512
#define E3_C    2048
#define NZ_C    32
#define D1_C    2048
#define D2_C    512
#define D3_C    512
#define K_C     100
#define EPS_C   1e-5f

// FFMA2 GEMM tiling: 128x128 tile, TK=8, 256 threads, 8x8 microtile, double-buffered
#define TM 128
#define TN 128
#define TK 8
#define MBLK (N_PTS / TM)                       // 232
#define MSE_PARTIALS (MBLK * (N_IN_C / TN))     // 232*8 = 1856

// small GEMM (N=32 layer) tiling
#define BM 128
#define BN 64
#define BK 16

// ---------------- scratch ----------------
__device__ float g_bufA[(size_t)N_PTS * 2048];
__device__ float g_bufB[(size_t)N_PTS * 2048];
__device__ float g_zbuf[(size_t)N_PTS * NZ_C];
__device__ float g_q[(size_t)K_C * N_PTS];      // TRANSPOSED: [K][N]
__device__ int   g_pred[N_PTS];
__device__ float g_Scon[N_PTS];
__device__ float g_u[K_C];
__device__ float g_f[K_C];
__device__ int   g_cnt[K_C];
__device__ float g_S;
__device__ float g_uloss;
__device__ float g_msep[MSE_PARTIALS];
__device__ float g_klp[MBLK];

__global__ void init_kernel() {
    int t = threadIdx.x;
    if (t < K_C) g_cnt[t] = 0;
}

// ---------------- packed fp32 helpers ----------------
__device__ __forceinline__ void ffma2(unsigned long long& acc,
                                      unsigned long long a,
                                      unsigned long long b) {
    asm("fma.rn.f32x2 %0, %1, %2, %0;" : "+l"(acc) : "l"(a), "l"(b));
}
union F4U {
    float4 f;
    unsigned long long u[2];
};

// ---------------- inner tile compute ----------------
__device__ __forceinline__ void compute_tile(
    const float (&As2)[TK][2 * TM], const float (&Ws)[TK][TN],
    unsigned long long (&acc)[8][4], int tx, int ty)
{
#pragma unroll
    for (int kk = 0; kk < TK; kk++) {
        F4U b0, b1;
        b0.f = *reinterpret_cast<const float4*>(&Ws[kk][tx * 4]);
        b1.f = *reinterpret_cast<const float4*>(&Ws[kk][64 + tx * 4]);
#pragma unroll
        for (int i = 0; i < 4; i++) {
            F4U a;
            a.f = *reinterpret_cast<const float4*>(&As2[kk][(ty * 8 + 2 * i) * 2]);
            ffma2(acc[2 * i][0],     a.u[0], b0.u[0]);
            ffma2(acc[2 * i][1],     a.u[0], b0.u[1]);
            ffma2(acc[2 * i][2],     a.u[0], b1.u[0]);
            ffma2(acc[2 * i][3],     a.u[0], b1.u[1]);
            ffma2(acc[2 * i + 1][0], a.u[1], b0.u[0]);
            ffma2(acc[2 * i + 1][1], a.u[1], b0.u[1]);
            ffma2(acc[2 * i + 1][2], a.u[1], b1.u[0]);
            ffma2(acc[2 * i + 1][3], a.u[1], b1.u[1]);
        }
    }
}

// ---------------- FFMA2 GEMM, double-buffered ----------------
// requires M%128==0, K%8==0, N%128==0
template <int DORELU, int DOMSE>
__global__ __launch_bounds__(256, 2) void gemm_ffma2(
    const float* __restrict__ A, const float* __restrict__ W,
    const float* __restrict__ bias, float* __restrict__ C,
    const float* __restrict__ Xref, float* __restrict__ partial,
    int M, int K, int N)
{
    __shared__ float As2[2][TK][2 * TM];   // duplicated A: 16 KB
    __shared__ float Ws[2][TK][TN];        // 8 KB
    const int tid = threadIdx.x;
    const int rowBlock = blockIdx.y * TM;
    const int colBlock = blockIdx.x * TN;
    const int tx = tid & 15;
    const int ty = tid >> 4;

    unsigned long long acc[8][4];
#pragma unroll
    for (int i = 0; i < 8; i++)
#pragma unroll
        for (int g = 0; g < 4; g++) acc[i][g] = 0ull;

    // global-load mappings
    const int aRow = tid >> 1;            // 0..127
    const int aKof = (tid & 1) * 4;       // 0 or 4
    const int wK   = tid >> 5;            // 0..7
    const int wC   = (tid & 31) * 4;      // 0..124

    const float* aPtr = &A[(size_t)(rowBlock + aRow) * K + aKof];
    const float* wPtr = &W[(size_t)wK * N + colBlock + wC];

    // prologue: tile 0
    {
        float4 av = *reinterpret_cast<const float4*>(aPtr);
        float4 wv = *reinterpret_cast<const float4*>(wPtr);
        *reinterpret_cast<float2*>(&As2[0][aKof + 0][2 * aRow]) = make_float2(av.x, av.x);
        *reinterpret_cast<float2*>(&As2[0][aKof + 1][2 * aRow]) = make_float2(av.y, av.y);
        *reinterpret_cast<float2*>(&As2[0][aKof + 2][2 * aRow]) = make_float2(av.z, av.z);
        *reinterpret_cast<float2*>(&As2[0][aKof + 3][2 * aRow]) = make_float2(av.w, av.w);
        *reinterpret_cast<float4*>(&Ws[0][wK][wC]) = wv;
    }
    __syncthreads();

    int buf = 0;
    for (int k0 = TK; k0 < K; k0 += TK) {
        float4 av = *reinterpret_cast<const float4*>(aPtr + k0);
        float4 wv = *reinterpret_cast<const float4*>(wPtr + (size_t)k0 * N);
        compute_tile(As2[buf], Ws[buf], acc, tx, ty);
        int nb = buf ^ 1;
        *reinterpret_cast<float2*>(&As2[nb][aKof + 0][2 * aRow]) = make_float2(av.x, av.x);
        *reinterpret_cast<float2*>(&As2[nb][aKof + 1][2 * aRow]) = make_float2(av.y, av.y);
        *reinterpret_cast<float2*>(&As2[nb][aKof + 2][2 * aRow]) = make_float2(av.z, av.z);
        *reinterpret_cast<float2*>(&As2[nb][aKof + 3][2 * aRow]) = make_float2(av.w, av.w);
        *reinterpret_cast<float4*>(&Ws[nb][wK][wC]) = wv;
        __syncthreads();
        buf = nb;
    }
    compute_tile(As2[buf], Ws[buf], acc, tx, ty);

    // epilogue
    const int rBase = ty * 8;
    float4 bs0 = *reinterpret_cast<const float4*>(&bias[colBlock + tx * 4]);
    float4 bs1 = *reinterpret_cast<const float4*>(&bias[colBlock + 64 + tx * 4]);

    if (DOMSE) {
        __shared__ float red[256];
        float mse = 0.f;
#pragma unroll
        for (int i = 0; i < 8; i++) {
            const float* xrow = &Xref[(size_t)(rowBlock + rBase + i) * N + colBlock];
            float4 x0 = *reinterpret_cast<const float4*>(&xrow[tx * 4]);
            float4 x1 = *reinterpret_cast<const float4*>(&xrow[64 + tx * 4]);
            F4U v0, v1;
            v0.u[0] = acc[i][0]; v0.u[1] = acc[i][1];
            v1.u[0] = acc[i][2]; v1.u[1] = acc[i][3];
            float d;
            d = v0.f.x + bs0.x - x0.x; mse = fmaf(d, d, mse);
            d = v0.f.y + bs0.y - x0.y; mse = fmaf(d, d, mse);
            d = v0.f.z + bs0.z - x0.z; mse = fmaf(d, d, mse);
            d = v0.f.w + bs0.w - x0.w; mse = fmaf(d, d, mse);
            d = v1.f.x + bs1.x - x1.x; mse = fmaf(d, d, mse);
            d = v1.f.y + bs1.y - x1.y; mse = fmaf(d, d, mse);
            d = v1.f.z + bs1.z - x1.z; mse = fmaf(d, d, mse);
            d = v1.f.w + bs1.w - x1.w; mse = fmaf(d, d, mse);
        }
        red[tid] = mse;
        __syncthreads();
        for (int o = 128; o > 0; o >>= 1) {
            if (tid < o) red[tid] += red[tid + o];
            __syncthreads();
        }
        if (tid == 0) partial[blockIdx.y * gridDim.x + blockIdx.x] = red[0];
    } else {
#pragma unroll
        for (int i = 0; i < 8; i++) {
            float* crow = &C[(size_t)(rowBlock + rBase + i) * N + colBlock];
            F4U v0, v1;
            v0.u[0] = acc[i][0]; v0.u[1] = acc[i][1];
            v1.u[0] = acc[i][2]; v1.u[1] = acc[i][3];
            v0.f.x += bs0.x; v0.f.y += bs0.y; v0.f.z += bs0.z; v0.f.w += bs0.w;
            v1.f.x += bs1.x; v1.f.y += bs1.y; v1.f.z += bs1.z; v1.f.w += bs1.w;
            if (DORELU) {
                v0.f.x = fmaxf(v0.f.x, 0.f); v0.f.y = fmaxf(v0.f.y, 0.f);
                v0.f.z = fmaxf(v0.f.z, 0.f); v0.f.w = fmaxf(v0.f.w, 0.f);
                v1.f.x = fmaxf(v1.f.x, 0.f); v1.f.y = fmaxf(v1.f.y, 0.f);
                v1.f.z = fmaxf(v1.f.z, 0.f); v1.f.w = fmaxf(v1.f.w, 0.f);
            }
            *reinterpret_cast<float4*>(&crow[tx * 4]) = v0.f;
            *reinterpret_cast<float4*>(&crow[64 + tx * 4]) = v1.f;
        }
    }
}

// ---------------- small-N fp32 GEMM (N=32 z layer) ----------------
__global__ __launch_bounds__(256) void gemm_relu(
    const float* __restrict__ A, const float* __restrict__ W,
    const float* __restrict__ bias, float* __restrict__ C,
    int M, int K, int N, int doRelu)
{
    __shared__ float As[BK][BM];
    __shared__ float Wsm[BK][BN];
    const int tid = threadIdx.x;
    const int rowBlock = blockIdx.y * BM;
    const int colBlock = blockIdx.x * BN;
    const int tx = tid & 15;
    const int ty = tid >> 4;
    const int rBase = ty * 8;
    const int cBase = tx * 4;

    float acc[8][4];
#pragma unroll
    for (int i = 0; i < 8; i++)
#pragma unroll
        for (int j = 0; j < 4; j++) acc[i][j] = 0.f;

    const int aRow0 = tid >> 2;
    const int aF4   = tid & 3;
    const int wK    = tid >> 4;
    const int wC    = (tid & 15) * 4;

    for (int k0 = 0; k0 < K; k0 += BK) {
#pragma unroll
        for (int h = 0; h < 2; h++) {
            int r = aRow0 + h * 64;
            float4 v = *reinterpret_cast<const float4*>(
                &A[(size_t)(rowBlock + r) * K + k0 + aF4 * 4]);
            As[aF4 * 4 + 0][r] = v.x;
            As[aF4 * 4 + 1][r] = v.y;
            As[aF4 * 4 + 2][r] = v.z;
            As[aF4 * 4 + 3][r] = v.w;
        }
        {
            int col = colBlock + wC;
            float4 v = make_float4(0.f, 0.f, 0.f, 0.f);
            if (col + 3 < N) {
                v = *reinterpret_cast<const float4*>(&W[(size_t)(k0 + wK) * N + col]);
            } else {
                float tmp[4] = {0.f, 0.f, 0.f, 0.f};
                for (int j = 0; j < 4; j++)
                    if (col + j < N) tmp[j] = W[(size_t)(k0 + wK) * N + col + j];
                v = make_float4(tmp[0], tmp[1], tmp[2], tmp[3]);
            }
            *reinterpret_cast<float4*>(&Wsm[wK][wC]) = v;
        }
        __syncthreads();
#pragma unroll
        for (int kk = 0; kk < BK; kk++) {
            float a[8], b[4];
#pragma unroll
            for (int i = 0; i < 8; i++) a[i] = As[kk][rBase + i];
#pragma unroll
            for (int j = 0; j < 4; j++) b[j] = Wsm[kk][cBase + j];
#pragma unroll
            for (int i = 0; i < 8; i++)
#pragma unroll
                for (int j = 0; j < 4; j++) acc[i][j] = fmaf(a[i], b[j], acc[i][j]);
        }
        __syncthreads();
    }
#pragma unroll
    for (int i = 0; i < 8; i++) {
        int row = rowBlock + rBase + i;
#pragma unroll
        for (int j = 0; j < 4; j++) {
            int col = colBlock + cBase + j;
            if (col < N) {
                float v = acc[i][j] + bias[col];
                if (doRelu) v = fmaxf(v, 0.f);
                C[(size_t)row * N + col] = v;
            }
        }
    }
}

// ---------------- pass A: per-point clustering stats (q transposed [K][N]) ----------------
__global__ __launch_bounds__(128) void passA(
    const float* __restrict__ z, const float* __restrict__ t1,
    const float* __restrict__ clus, float* __restrict__ q,
    int* __restrict__ pred, float* __restrict__ scon,
    float* __restrict__ out, int out_size)
{
    __shared__ float cs[K_C * NZ_C];
    const int tid = threadIdx.x;
    for (int i = tid; i < K_C * NZ_C; i += 128) cs[i] = clus[i];
    __syncthreads();

    const int n = blockIdx.x * 128 + tid;
    if (n >= N_PTS) return;

    const float tx = t1[n * 3 + 0] * 0.01f;
    const float ty = t1[n * 3 + 1] * 0.01f;
    const float tz = t1[n * 3 + 2] * 0.01f;
    const float cm = tx * ty * tz * 0.99f + 1.0f;

    float zp[NZ_C];
    const float* zr = &z[(size_t)n * NZ_C];
    float mean = 0.f;
#pragma unroll
    for (int i = 0; i < NZ_C; i++) { zp[i] = zr[i] * cm; mean += zp[i]; }
    mean *= (1.0f / NZ_C);
    float var = 0.f;
#pragma unroll
    for (int i = 0; i < NZ_C; i++) { float d = zp[i] - mean; var += d * d; }
    var *= (1.0f / (NZ_C - 1));
    const float invstd = 1.0f / sqrtf(var);
#pragma unroll
    for (int i = 0; i < NZ_C; i++) zp[i] = (zp[i] - mean) * invstd;

    float qsum = 0.f;
    float best = -1.f;
    int bestk = 0;
    for (int k = 0; k < K_C; k++) {
        const float* c = &cs[k * NZ_C];
        float d = 0.f;
#pragma unroll
        for (int i = 0; i < NZ_C; i++) { float df = zp[i] - c[i]; d = fmaf(df, df, d); }
        float qr = EPS_C + d;
        q[(size_t)k * N_PTS + n] = qr;   // coalesced store
        qsum += qr;
        if (qr > best) { best = qr; bestk = k; }
    }
    const float inv = 1.0f / qsum;
    float s = 0.f;
    for (int k = 0; k < K_C; k++) {
        float qn = q[(size_t)k * N_PTS + n] * inv;
        q[(size_t)k * N_PTS + n] = qn;
        float l = logf(qn);
        float t = 1.0f - qn;
        float neg_temp = t * t * (-l) * (float)N_PTS;
        s += 1.0f / sqrtf(neg_temp);
    }
    pred[n] = bestk;
    scon[n] = s;
    if (n < out_size) out[n] = (float)bestk;
    atomicAdd(&g_cnt[bestk], 1);
}

// ---------------- u[k] = sum_n q[k][n] (coalesced) ----------------
__global__ void ureduce(const float* __restrict__ q) {
    __shared__ float sh[256];
    const int k = blockIdx.x;
    float s = 0.f;
    for (int n = threadIdx.x; n < N_PTS; n += 256) s += q[(size_t)k * N_PTS + n];
    sh[threadIdx.x] = s;
    __syncthreads();
    for (int o = 128; o > 0; o >>= 1) {
        if (threadIdx.x < o) sh[threadIdx.x] += sh[threadIdx.x + o];
        __syncthreads();
    }
    if (threadIdx.x == 0) g_u[k] = sh[0];
}

__global__ void sreduce(const float* __restrict__ scon) {
    __shared__ float sh[256];
    float s = 0.f;
    for (int n = threadIdx.x; n < N_PTS; n += 256) s += scon[n];
    sh[threadIdx.x] = s;
    __syncthreads();
    for (int o = 128; o > 0; o >>= 1) {
        if (threadIdx.x < o) sh[threadIdx.x] += sh[threadIdx.x + o];
        __syncthreads();
    }
    if (threadIdx.x == 0) g_S = sh[0];
}

// ---------------- pass B: f[k], u_loss ----------------
__global__ void passB(const float* __restrict__ clus) {
    __shared__ float sh[256];
    const int tid = threadIdx.x;
    float s = 0.f;
    for (int p = tid; p < K_C * K_C; p += 256) {
        int i = p / K_C, j = p - i * K_C;
        const float* a = &clus[i * NZ_C];
        const float* b = &clus[j * NZ_C];
        float d = 0.f;
#pragma unroll
        for (int t = 0; t < NZ_C; t++) { float df = a[t] - b[t]; d = fmaf(df, df, d); }
        s += d;
    }
    sh[tid] = s;
    __syncthreads();
    for (int o = 128; o > 0; o >>= 1) {
        if (tid < o) sh[tid] += sh[tid + o];
        __syncthreads();
    }
    if (tid == 0) {
        float md = sh[0] / (float)(K_C * K_C - K_C);
        g_uloss = 0.01f / md;

        float un[K_C], vn[K_C];
        float um = 0.f;
        for (int k = 0; k < K_C; k++) um += g_u[k];
        um /= (float)K_C;
        float uv = 0.f;
        for (int k = 0; k < K_C; k++) { float d = g_u[k] - um; uv += d * d; }
        uv /= (float)(K_C - 1);
        float uis = 1.0f / sqrtf(uv);
        for (int k = 0; k < K_C; k++) un[k] = (g_u[k] - um) * uis;

        float S = g_S;
        float vm = 0.f;
        for (int k = 0; k < K_C; k++) {
            float nc = (g_cnt[k] > 0) ? (float)g_cnt[k] : 1.0f;
            vn[k] = sqrtf(nc) * S;
            vm += vn[k];
        }
        vm /= (float)K_C;
        float vv = 0.f;
        for (int k = 0; k < K_C; k++) { float d = vn[k] - vm; vv += d * d; }
        vv /= (float)(K_C - 1);
        float vis = 1.0f / sqrtf(vv);
        for (int k = 0; k < K_C; k++) vn[k] = (vn[k] - vm) * vis;

        float umin = un[0], vmin = vn[0];
        for (int k = 1; k < K_C; k++) {
            umin = fminf(umin, un[k]);
            vmin = fminf(vmin, vn[k]);
        }
        for (int k = 0; k < K_C; k++) {
            g_f[k] = (un[k] - umin + 0.001f) + (vn[k] - vmin + 0.001f) + 1.0f;
        }
    }
}

// ---------------- pass C: KL partials (q transposed) ----------------
__global__ __launch_bounds__(128) void passC(const float* __restrict__ q,
                                             float* __restrict__ klp) {
    __shared__ float fsh[K_C];
    __shared__ float sh[128];
    const int tid = threadIdx.x;
    for (int i = tid; i < K_C; i += 128) fsh[i] = g_f[i];
    __syncthreads();
    const int n = blockIdx.x * 128 + tid;
    float kl = 0.f;
    float ws = 0.f;
    for (int k = 0; k < K_C; k++) {
        float qv = q[(size_t)k * N_PTS + n];
        ws += qv * qv / fsh[k];
    }
    float inv = 1.0f / ws;
    for (int k = 0; k < K_C; k++) {
        float qv = q[(size_t)k * N_PTS + n];
        float p = qv * qv / fsh[k] * inv;
        kl += p * (logf(p) - logf(qv));
    }
    sh[tid] = kl;
    __syncthreads();
    for (int o = 64; o > 0; o >>= 1) {
        if (tid < o) sh[tid] += sh[tid + o];
        __syncthreads();
    }
    if (tid == 0) klp[blockIdx.x] = sh[0];
}

// ---------------- final: loss scalar ----------------
__global__ void finalk(float* __restrict__ out, int out_size) {
    __shared__ float sh[256];
    __shared__ float tot[2];
    const int tid = threadIdx.x;
    float s = 0.f;
    for (int i = tid; i < MSE_PARTIALS; i += 256) s += g_msep[i];
    sh[tid] = s;
    __syncthreads();
    for (int o = 128; o > 0; o >>= 1) {
        if (tid < o) sh[tid] += sh[tid + o];
        __syncthreads();
    }
    if (tid == 0) tot[0] = sh[0];
    __syncthreads();
    s = 0.f;
    for (int i = tid; i < MBLK; i += 256) s += g_klp[i];
    sh[tid] = s;
    __syncthreads();
    for (int o = 128; o > 0; o >>= 1) {
        if (tid < o) sh[tid] += sh[tid + o];
        __syncthreads();
    }
    if (tid == 0) tot[1] = sh[0];
    __syncthreads();
    if (tid == 0) {
        float re_loss = tot[0] / ((float)N_PTS * (float)N_IN_C);
        float kl_loss = tot[1] / ((float)N_PTS * (float)K_C) * 0.01f;
        float loss = kl_loss + re_loss + g_uloss;
        if (out_size > N_PTS) out[N_PTS] = loss;
    }
}

// ---------------- launch ----------------
extern "C" void kernel_launch(void* const* d_in, const int* in_sizes, int n_in,
                              void* d_out, int out_size) {
    const float* x    = (const float*)d_in[0];
    const float* t1   = (const float*)d_in[1];
    const float* clus = (const float*)d_in[2];
    const float* We1  = (const float*)d_in[3];
    const float* be1  = (const float*)d_in[4];
    const float* We2  = (const float*)d_in[5];
    const float* be2  = (const float*)d_in[6];
    const float* We3  = (const float*)d_in[7];
    const float* be3  = (const float*)d_in[8];
    const float* Wz   = (const float*)d_in[9];
    const float* bz   = (const float*)d_in[10];
    const float* Wd1  = (const float*)d_in[11];
    const float* bd1  = (const float*)d_in[12];
    const float* Wd2  = (const float*)d_in[13];
    const float* bd2  = (const float*)d_in[14];
    const float* Wd3  = (const float*)d_in[15];
    const float* bd3  = (const float*)d_in[16];
    const float* Wxb  = (const float*)d_in[17];
    const float* bxb  = (const float*)d_in[18];
    float* out = (float*)d_out;

    float *bufA, *bufB, *zbuf, *qbuf, *scon, *msep, *klp;
    int *pred;
    cudaGetSymbolAddress((void**)&bufA, g_bufA);
    cudaGetSymbolAddress((void**)&bufB, g_bufB);
    cudaGetSymbolAddress((void**)&zbuf, g_zbuf);
    cudaGetSymbolAddress((void**)&qbuf, g_q);
    cudaGetSymbolAddress((void**)&pred, g_pred);
    cudaGetSymbolAddress((void**)&scon, g_Scon);
    cudaGetSymbolAddress((void**)&msep, g_msep);
    cudaGetSymbolAddress((void**)&klp,  g_klp);

    init_kernel<<<1, 128>>>();

    // encoder
    gemm_ffma2<1, 0><<<dim3(E1_C / TN, MBLK), 256>>>(x,    We1, be1, bufA, nullptr, nullptr, N_PTS, N_IN_C, E1_C);
    gemm_ffma2<1, 0><<<dim3(E2_C / TN, MBLK), 256>>>(bufA, We2, be2, bufB, nullptr, nullptr, N_PTS, E1_C,  E2_C);
    gemm_ffma2<1, 0><<<dim3(E3_C / TN, MBLK), 256>>>(bufB, We3, be3, bufA, nullptr, nullptr, N_PTS, E2_C,  E3_C);
    gemm_relu<<<dim3(1, N_PTS / BM), 256>>>(bufA, Wz, bz, zbuf, N_PTS, E3_C, NZ_C, 0);
    // decoder
    gemm_ffma2<1, 0><<<dim3(D1_C / TN, MBLK), 256>>>(zbuf, Wd1, bd1, bufB, nullptr, nullptr, N_PTS, NZ_C, D1_C);
    gemm_ffma2<1, 0><<<dim3(D2_C / TN, MBLK), 256>>>(bufB, Wd2, bd2, bufA, nullptr, nullptr, N_PTS, D1_C, D2_C);
    gemm_ffma2<1, 0><<<dim3(D3_C / TN, MBLK), 256>>>(bufA, Wd3, bd3, bufB, nullptr, nullptr, N_PTS, D2_C, D3_C);
    gemm_ffma2<0, 1><<<dim3(N_IN_C / TN, MBLK), 256>>>(bufB, Wxb, bxb, nullptr, x, msep, N_PTS, D3_C, N_IN_C);

    // clustering
    passA<<<MBLK, 128>>>(zbuf, t1, clus, qbuf, pred, scon, out, out_size);
    ureduce<<<K_C, 256>>>(qbuf);
    sreduce<<<1, 256>>>(scon);
    passB<<<1, 256>>>(clus);
    passC<<<MBLK, 128>>>(qbuf, klp);
    finalk<<<1, 256>>>(out, out_size);
}